// round 1
// baseline (speedup 1.0000x reference)
#include <cuda_runtime.h>
#include <float.h>

#define Bb 2
#define Ss 2048
#define Dd 768
#define Hh 12
#define DH 64
#define Mm (Bb*Ss)

// Scratch (no allocations allowed in kernel_launch)
__device__ float g_Q[(size_t)Bb*Hh*Ss*DH];
__device__ float g_K[(size_t)Bb*Hh*Ss*DH];
__device__ float g_V[(size_t)Bb*Hh*Ss*DH];
__device__ float g_O[(size_t)Mm*Dd];

// ---------------------------------------------------------------------------
// GEMM C = A[M,K] @ W[N,K]^T  (both K-contiguous), BM=BN=64, BK=16,
// 256 threads, 4x4 register tile per thread.
// ---------------------------------------------------------------------------

__global__ __launch_bounds__(256) void gemm_qkv(
    const float* __restrict__ X,
    const float* __restrict__ Wq,
    const float* __restrict__ Wk,
    const float* __restrict__ Wv)
{
    __shared__ float As[16][68];
    __shared__ float Bs[16][68];

    const float* W   = (blockIdx.z == 0) ? Wq : (blockIdx.z == 1 ? Wk : Wv);
    float*       Obuf= (blockIdx.z == 0) ? g_Q : (blockIdx.z == 1 ? g_K : g_V);

    const int tid = threadIdx.x;
    const int tx = tid & 15;
    const int ty = tid >> 4;
    const int mBase = blockIdx.x * 64;
    const int h = blockIdx.y;           // N-tile == head (BN=64=Dh)
    const int nBase = h * 64;

    const int ldr = tid >> 2;           // 0..63 row in tile
    const int ldc = (tid & 3) << 2;     // 0,4,8,12 k in tile

    float acc[4][4];
    #pragma unroll
    for (int i = 0; i < 4; i++)
        #pragma unroll
        for (int j = 0; j < 4; j++) acc[i][j] = 0.f;

    for (int k0 = 0; k0 < Dd; k0 += 16) {
        float4 av = *(const float4*)(X + (size_t)(mBase + ldr) * Dd + k0 + ldc);
        float4 bv = *(const float4*)(W + (size_t)(nBase + ldr) * Dd + k0 + ldc);
        As[ldc+0][ldr] = av.x; As[ldc+1][ldr] = av.y;
        As[ldc+2][ldr] = av.z; As[ldc+3][ldr] = av.w;
        Bs[ldc+0][ldr] = bv.x; Bs[ldc+1][ldr] = bv.y;
        Bs[ldc+2][ldr] = bv.z; Bs[ldc+3][ldr] = bv.w;
        __syncthreads();
        #pragma unroll
        for (int kk = 0; kk < 16; kk++) {
            float4 a4 = *(const float4*)&As[kk][ty << 2];
            float4 b4 = *(const float4*)&Bs[kk][tx << 2];
            float ar[4] = {a4.x, a4.y, a4.z, a4.w};
            float br[4] = {b4.x, b4.y, b4.z, b4.w};
            #pragma unroll
            for (int i = 0; i < 4; i++)
                #pragma unroll
                for (int j = 0; j < 4; j++)
                    acc[i][j] += ar[i] * br[j];
        }
        __syncthreads();
    }

    // Scatter epilogue into [B, H, S, Dh] head layout.
    #pragma unroll
    for (int i = 0; i < 4; i++) {
        int row = mBase + (ty << 2) + i;     // 0..4095 = b*S + s
        int bb = row >> 11;                  // /2048
        int ss = row & 2047;
        size_t idx = (((size_t)bb * Hh + h) * Ss + ss) * DH + (tx << 2);
        *(float4*)(Obuf + idx) = make_float4(acc[i][0], acc[i][1], acc[i][2], acc[i][3]);
    }
}

__global__ __launch_bounds__(256) void gemm_out(
    const float* __restrict__ Wo,
    float* __restrict__ C)
{
    __shared__ float As[16][68];
    __shared__ float Bs[16][68];

    const int tid = threadIdx.x;
    const int tx = tid & 15;
    const int ty = tid >> 4;
    const int mBase = blockIdx.x * 64;
    const int nBase = blockIdx.y * 64;

    const int ldr = tid >> 2;
    const int ldc = (tid & 3) << 2;

    float acc[4][4];
    #pragma unroll
    for (int i = 0; i < 4; i++)
        #pragma unroll
        for (int j = 0; j < 4; j++) acc[i][j] = 0.f;

    for (int k0 = 0; k0 < Dd; k0 += 16) {
        float4 av = *(const float4*)(g_O + (size_t)(mBase + ldr) * Dd + k0 + ldc);
        float4 bv = *(const float4*)(Wo  + (size_t)(nBase + ldr) * Dd + k0 + ldc);
        As[ldc+0][ldr] = av.x; As[ldc+1][ldr] = av.y;
        As[ldc+2][ldr] = av.z; As[ldc+3][ldr] = av.w;
        Bs[ldc+0][ldr] = bv.x; Bs[ldc+1][ldr] = bv.y;
        Bs[ldc+2][ldr] = bv.z; Bs[ldc+3][ldr] = bv.w;
        __syncthreads();
        #pragma unroll
        for (int kk = 0; kk < 16; kk++) {
            float4 a4 = *(const float4*)&As[kk][ty << 2];
            float4 b4 = *(const float4*)&Bs[kk][tx << 2];
            float ar[4] = {a4.x, a4.y, a4.z, a4.w};
            float br[4] = {b4.x, b4.y, b4.z, b4.w};
            #pragma unroll
            for (int i = 0; i < 4; i++)
                #pragma unroll
                for (int j = 0; j < 4; j++)
                    acc[i][j] += ar[i] * br[j];
        }
        __syncthreads();
    }

    #pragma unroll
    for (int i = 0; i < 4; i++) {
        int row = mBase + (ty << 2) + i;
        *(float4*)(C + (size_t)row * Dd + nBase + (tx << 2)) =
            make_float4(acc[i][0], acc[i][1], acc[i][2], acc[i][3]);
    }
}

// ---------------------------------------------------------------------------
// Flash attention, fp32, causal. 64x64 tiles, 256 threads, 4x4 register tiles.
// Q/K stored transposed ([d][row], stride 68), V natural ([row][d], stride 68).
// ---------------------------------------------------------------------------

__global__ __launch_bounds__(256) void attn_kernel()
{
    extern __shared__ float sm[];
    float* Qt = sm;                 // [64][68]  Qt[d][r]
    float* Kt = Qt + 64 * 68;       // [64][68]  Kt[d][c]
    float* Vs = Kt + 64 * 68;       // [64][68]  Vs[c][d]
    float* Ps = Vs + 64 * 68;       // [64][68]  Ps[r][c]

    const int tid = threadIdx.x;
    const int tx = tid & 15;
    const int ty = tid >> 4;
    const int qt = blockIdx.x;
    const int h  = blockIdx.y;
    const int b  = blockIdx.z;

    const float* Qg = g_Q + (((size_t)b * Hh + h) * Ss + (size_t)qt * 64) * DH;
    const float* Kg = g_K + (((size_t)b * Hh + h) * Ss) * DH;
    const float* Vg = g_V + (((size_t)b * Hh + h) * Ss) * DH;

    const int ldr   = tid >> 2;          // 0..63
    const int dbase = (tid & 3) << 2;    // 0,4,8,12

    // Load Q tile transposed (read coalesced, scatter to smem).
    #pragma unroll
    for (int it = 0; it < 4; it++) {
        int d = dbase + it * 16;
        float4 v = *(const float4*)(Qg + ldr * DH + d);
        Qt[(d+0)*68 + ldr] = v.x;
        Qt[(d+1)*68 + ldr] = v.y;
        Qt[(d+2)*68 + ldr] = v.z;
        Qt[(d+3)*68 + ldr] = v.w;
    }

    float o[4][4];
    float mrow[4], lrow[4];
    #pragma unroll
    for (int i = 0; i < 4; i++) {
        mrow[i] = -FLT_MAX;
        lrow[i] = 0.f;
        #pragma unroll
        for (int j = 0; j < 4; j++) o[i][j] = 0.f;
    }

    const float SC = 0.125f;  // 1/sqrt(64)

    for (int kt = 0; kt <= qt; kt++) {
        __syncthreads();  // prior PV reads + Qt writes (first iter) complete

        const float* Kp = Kg + (size_t)kt * 64 * DH;
        const float* Vp = Vg + (size_t)kt * 64 * DH;
        #pragma unroll
        for (int it = 0; it < 4; it++) {
            int d = dbase + it * 16;
            float4 kv = *(const float4*)(Kp + ldr * DH + d);
            Kt[(d+0)*68 + ldr] = kv.x;
            Kt[(d+1)*68 + ldr] = kv.y;
            Kt[(d+2)*68 + ldr] = kv.z;
            Kt[(d+3)*68 + ldr] = kv.w;
            float4 vv = *(const float4*)(Vp + ldr * DH + d);
            *(float4*)(Vs + ldr * 68 + d) = vv;
        }
        __syncthreads();

        // S = Q @ K^T  (per-thread 4x4: rows ty*4+i, cols tx*4+j)
        float s[4][4];
        #pragma unroll
        for (int i = 0; i < 4; i++)
            #pragma unroll
            for (int j = 0; j < 4; j++) s[i][j] = 0.f;

        #pragma unroll 8
        for (int d = 0; d < 64; d++) {
            float4 a4 = *(const float4*)(Qt + d * 68 + (ty << 2));
            float4 k4 = *(const float4*)(Kt + d * 68 + (tx << 2));
            float ar[4] = {a4.x, a4.y, a4.z, a4.w};
            float kr[4] = {k4.x, k4.y, k4.z, k4.w};
            #pragma unroll
            for (int i = 0; i < 4; i++)
                #pragma unroll
                for (int j = 0; j < 4; j++)
                    s[i][j] += ar[i] * kr[j];
        }

        // Scale + causal mask (only diagonal tile needs it)
        #pragma unroll
        for (int i = 0; i < 4; i++)
            #pragma unroll
            for (int j = 0; j < 4; j++) {
                float v = s[i][j] * SC;
                if (kt == qt && ((tx << 2) + j) > ((ty << 2) + i)) v = -1e30f;
                s[i][j] = v;
            }

        // Row max: within-thread then 16-lane shuffle group
        float tm[4];
        #pragma unroll
        for (int i = 0; i < 4; i++)
            tm[i] = fmaxf(fmaxf(s[i][0], s[i][1]), fmaxf(s[i][2], s[i][3]));
        #pragma unroll
        for (int off = 1; off < 16; off <<= 1)
            #pragma unroll
            for (int i = 0; i < 4; i++)
                tm[i] = fmaxf(tm[i], __shfl_xor_sync(0xffffffffu, tm[i], off));

        float mnew[4], corr[4];
        #pragma unroll
        for (int i = 0; i < 4; i++) {
            mnew[i] = fmaxf(mrow[i], tm[i]);
            corr[i] = __expf(mrow[i] - mnew[i]);
            mrow[i] = mnew[i];
        }

        float rs[4];
        #pragma unroll
        for (int i = 0; i < 4; i++) {
            rs[i] = 0.f;
            #pragma unroll
            for (int j = 0; j < 4; j++) {
                float p = __expf(s[i][j] - mnew[i]);
                s[i][j] = p;
                rs[i] += p;
            }
        }
        #pragma unroll
        for (int off = 1; off < 16; off <<= 1)
            #pragma unroll
            for (int i = 0; i < 4; i++)
                rs[i] += __shfl_xor_sync(0xffffffffu, rs[i], off);

        #pragma unroll
        for (int i = 0; i < 4; i++) {
            lrow[i] = lrow[i] * corr[i] + rs[i];
            #pragma unroll
            for (int j = 0; j < 4; j++) o[i][j] *= corr[i];
        }

        // Publish P tile
        #pragma unroll
        for (int i = 0; i < 4; i++)
            *(float4*)(Ps + ((ty << 2) + i) * 68 + (tx << 2)) =
                make_float4(s[i][0], s[i][1], s[i][2], s[i][3]);
        __syncthreads();

        // O += P @ V  (thread: rows ty*4+i, dims tx*4+j)
        #pragma unroll 8
        for (int c = 0; c < 64; c++) {
            float4 vv = *(const float4*)(Vs + c * 68 + (tx << 2));
            float vr[4] = {vv.x, vv.y, vv.z, vv.w};
            float p0 = Ps[((ty << 2) + 0) * 68 + c];
            float p1 = Ps[((ty << 2) + 1) * 68 + c];
            float p2 = Ps[((ty << 2) + 2) * 68 + c];
            float p3 = Ps[((ty << 2) + 3) * 68 + c];
            #pragma unroll
            for (int j = 0; j < 4; j++) {
                o[0][j] += p0 * vr[j];
                o[1][j] += p1 * vr[j];
                o[2][j] += p2 * vr[j];
                o[3][j] += p3 * vr[j];
            }
        }
    }

    // Epilogue: normalize and write into [B*S, D] layout for the Wo GEMM.
    #pragma unroll
    for (int i = 0; i < 4; i++) {
        float inv = 1.f / lrow[i];
        int rglob = qt * 64 + (ty << 2) + i;
        size_t idx = ((size_t)b * Ss + rglob) * Dd + h * DH + (tx << 2);
        *(float4*)(g_O + idx) =
            make_float4(o[i][0] * inv, o[i][1] * inv, o[i][2] * inv, o[i][3] * inv);
    }
}

// ---------------------------------------------------------------------------

extern "C" void kernel_launch(void* const* d_in, const int* in_sizes, int n_in,
                              void* d_out, int out_size)
{
    const float* x  = (const float*)d_in[0];
    const float* Wq = (const float*)d_in[1];
    const float* Wk = (const float*)d_in[2];
    const float* Wv = (const float*)d_in[3];
    const float* Wo = (const float*)d_in[4];
    float* out = (float*)d_out;

    const int ATTN_SMEM = 4 * 64 * 68 * (int)sizeof(float);  // 69632 B
    cudaFuncSetAttribute(attn_kernel,
                         cudaFuncAttributeMaxDynamicSharedMemorySize, ATTN_SMEM);

    gemm_qkv<<<dim3(Mm / 64, Hh, 3), 256>>>(x, Wq, Wk, Wv);
    attn_kernel<<<dim3(Ss / 64, Hh, Bb), 256, ATTN_SMEM>>>();
    gemm_out<<<dim3(Mm / 64, Dd / 64), 256>>>(Wo, out);
}

// round 3
// speedup vs baseline: 2.8134x; 2.8134x over previous
#include <cuda_runtime.h>
#include <float.h>
#include <stdint.h>

#define Bb 2
#define Ss 2048
#define Dd 768
#define Hh 12
#define DH 64
#define Mm (Bb*Ss)

// ---------------- scratch ----------------
__device__ float g_Q[(size_t)Bb*Hh*Ss*DH];
__device__ float g_K[(size_t)Bb*Hh*Ss*DH];
__device__ float g_V[(size_t)Bb*Hh*Ss*DH];
__device__ float g_O[(size_t)Mm*Dd];
__device__ float g_Xc[(size_t)Mm*Dd];
__device__ float g_Wq[(size_t)Dd*Dd];
__device__ float g_Wk[(size_t)Dd*Dd];
__device__ float g_Wv[(size_t)Dd*Dd];
__device__ float g_Wo[(size_t)Dd*Dd];

// ---------------- helpers ----------------
__device__ __forceinline__ uint32_t smem_u32(const void* p) {
    uint32_t a;
    asm("{ .reg .u64 t; cvta.to.shared.u64 t, %1; cvt.u32.u64 %0, t; }" : "=r"(a) : "l"(p));
    return a;
}
__device__ __forceinline__ void cp16(uint32_t dst, const float* src) {
    asm volatile("cp.async.cg.shared.global [%0], [%1], 16;"
        :: "r"(dst), "l"(__cvta_generic_to_global(src)));
}
__device__ __forceinline__ void cp_commit() { asm volatile("cp.async.commit_group;"); }
__device__ __forceinline__ void cp_wait0()  { asm volatile("cp.async.wait_group 0;"); }
__device__ __forceinline__ void cp_wait2()  { asm volatile("cp.async.wait_group 2;"); }

__device__ __forceinline__ float to_tf32(float x) {
    uint32_t u;
    asm("cvt.rna.tf32.f32 %0, %1;" : "=r"(u) : "f"(x));
    return __uint_as_float(u);
}

// d += a(tf32 m16k8) * b(tf32 k8n8)
__device__ __forceinline__ void mma8(float* d, const uint32_t* a, const uint32_t* b) {
    asm volatile("mma.sync.aligned.m16n8k8.row.col.f32.tf32.tf32.f32 "
        "{%0,%1,%2,%3}, {%4,%5,%6,%7}, {%8,%9}, {%0,%1,%2,%3};"
        : "+f"(d[0]), "+f"(d[1]), "+f"(d[2]), "+f"(d[3])
        : "r"(a[0]), "r"(a[1]), "r"(a[2]), "r"(a[3]), "r"(b[0]), "r"(b[1]));
}
__device__ __forceinline__ uint32_t f2u(float x) { return __float_as_uint(x); }

// ---------------- tf32 rounding pre-pass ----------------
__global__ void conv_all(const float* __restrict__ x,
                         const float* __restrict__ wq, const float* __restrict__ wk,
                         const float* __restrict__ wv, const float* __restrict__ wo) {
    int i = blockIdx.x * blockDim.x + threadIdx.x;
    int stride = gridDim.x * blockDim.x;
    for (int t = i; t < Mm * Dd; t += stride) g_Xc[t] = to_tf32(x[t]);
    for (int t = i; t < Dd * Dd; t += stride) {
        g_Wq[t] = to_tf32(wq[t]);
        g_Wk[t] = to_tf32(wk[t]);
        g_Wv[t] = to_tf32(wv[t]);
        g_Wo[t] = to_tf32(wo[t]);
    }
}

// ---------------- tf32 warp-MMA GEMM ----------------
// acc[4][8][4]: warp tile 64x64 (4 mtiles x 8 ntiles), CTA 128x128, BK=16, 4 warps.
// A[M,768], B[N,768] both K-major (tf32-rounded). smem stage = A[128][20]+B[128][20].
#define GSTG 5120           // floats per stage
#define GCH  48             // 768/16 chunks

__device__ __forceinline__ void gemm_core(const float* __restrict__ Arow,
                                          const float* __restrict__ Brow,
                                          float* sm, float acc[4][8][4]) {
    const int tid = threadIdx.x;
    const int lane = tid & 31;
    const int wid = tid >> 5;
    const int wm = wid >> 1, wn = wid & 1;

    uint32_t sA = smem_u32(sm);
    uint32_t sB = sA + 2560u * 4u;

    #pragma unroll
    for (int mt = 0; mt < 4; mt++)
        #pragma unroll
        for (int nt = 0; nt < 8; nt++)
            #pragma unroll
            for (int q = 0; q < 4; q++) acc[mt][nt][q] = 0.f;

    // prologue: chunks 0..2 into stages 0..2
    #pragma unroll
    for (int c = 0; c < 3; c++) {
        uint32_t da = sA + c * GSTG * 4 + (tid * 20) * 4;
        uint32_t db = sB + c * GSTG * 4 + (tid * 20) * 4;
        const float* ga = Arow + (size_t)tid * Dd + c * 16;
        const float* gb = Brow + (size_t)tid * Dd + c * 16;
        #pragma unroll
        for (int q = 0; q < 4; q++) { cp16(da + q * 16, ga + q * 4); cp16(db + q * 16, gb + q * 4); }
        cp_commit();
    }

    const int rA = wm * 64 + (lane >> 2);       // A row base within tile
    const int rB = wn * 64 + (lane >> 2);
    const int cL = lane & 3;

    for (int c = 0; c < GCH; c++) {
        cp_wait2();
        __syncthreads();
        // prefetch chunk c+3
        if (c + 3 < GCH) {
            int st = (c + 3) & 3;
            uint32_t da = sA + st * GSTG * 4 + (tid * 20) * 4;
            uint32_t db = sB + st * GSTG * 4 + (tid * 20) * 4;
            const float* ga = Arow + (size_t)tid * Dd + (c + 3) * 16;
            const float* gb = Brow + (size_t)tid * Dd + (c + 3) * 16;
            #pragma unroll
            for (int q = 0; q < 4; q++) { cp16(da + q * 16, ga + q * 4); cp16(db + q * 16, gb + q * 4); }
        }
        cp_commit();

        const float* As = sm + (c & 3) * GSTG;
        const float* Bs = As + 2560;
        #pragma unroll
        for (int ks = 0; ks < 2; ks++) {
            const int kb = ks * 8 + cL;
            uint32_t b[8][2];
            #pragma unroll
            for (int nt = 0; nt < 8; nt++) {
                const float* bp = Bs + (rB + nt * 8) * 20;
                b[nt][0] = f2u(bp[kb]);
                b[nt][1] = f2u(bp[kb + 4]);
            }
            #pragma unroll
            for (int mt = 0; mt < 4; mt++) {
                const float* ap = As + (rA + mt * 16) * 20;
                uint32_t a[4];
                a[0] = f2u(ap[kb]);
                a[1] = f2u(ap[8 * 20 + kb]);
                a[2] = f2u(ap[kb + 4]);
                a[3] = f2u(ap[8 * 20 + kb + 4]);
                #pragma unroll
                for (int nt = 0; nt < 8; nt++) mma8(acc[mt][nt], a, b[nt]);
            }
        }
    }
}

// QKV projection: C scatter into [B,H,S,DH]; z==0 pre-scales by 1/8 and all rna-rounded.
__global__ __launch_bounds__(128) void gemm_qkv_tc() {
    extern __shared__ float sm[];
    const int z = blockIdx.z;
    const float* W = (z == 0) ? g_Wq : (z == 1 ? g_Wk : g_Wv);
    float* Obuf = (z == 0) ? g_Q : (z == 1 ? g_K : g_V);
    const float scale = (z == 0) ? 0.125f : 1.0f;
    const int mBase = blockIdx.x * 128, nBase = blockIdx.y * 128;

    float acc[4][8][4];
    gemm_core(g_Xc + (size_t)mBase * Dd, W + (size_t)nBase * Dd, sm, acc);

    const int lane = threadIdx.x & 31, wid = threadIdx.x >> 5;
    const int wm = wid >> 1, wn = wid & 1;
    const int h = (nBase + wn * 64) >> 6;
    #pragma unroll
    for (int mt = 0; mt < 4; mt++) {
        int r0 = mBase + wm * 64 + mt * 16 + (lane >> 2);
        #pragma unroll
        for (int half = 0; half < 2; half++) {
            int row = r0 + half * 8;
            int bb = row >> 11, ssi = row & 2047;
            float* dst = Obuf + (((size_t)bb * Hh + h) * Ss + ssi) * DH;
            #pragma unroll
            for (int nt = 0; nt < 8; nt++) {
                int d = nt * 8 + 2 * (lane & 3);
                float v0 = to_tf32(acc[mt][nt][half * 2 + 0] * scale);
                float v1 = to_tf32(acc[mt][nt][half * 2 + 1] * scale);
                *(float2*)(dst + d) = make_float2(v0, v1);
            }
        }
    }
}

// output projection: plain fp32 store
__global__ __launch_bounds__(128) void gemm_out_tc(float* __restrict__ C) {
    extern __shared__ float sm[];
    const int mBase = blockIdx.x * 128, nBase = blockIdx.y * 128;

    float acc[4][8][4];
    gemm_core(g_O + (size_t)mBase * Dd, g_Wo + (size_t)nBase * Dd, sm, acc);

    const int lane = threadIdx.x & 31, wid = threadIdx.x >> 5;
    const int wm = wid >> 1, wn = wid & 1;
    #pragma unroll
    for (int mt = 0; mt < 4; mt++) {
        int r0 = mBase + wm * 64 + mt * 16 + (lane >> 2);
        #pragma unroll
        for (int half = 0; half < 2; half++) {
            int row = r0 + half * 8;
            float* dst = C + (size_t)row * Dd + nBase + wn * 64;
            #pragma unroll
            for (int nt = 0; nt < 8; nt++) {
                int d = nt * 8 + 2 * (lane & 3);
                *(float2*)(dst + d) = make_float2(acc[mt][nt][half * 2 + 0],
                                                  acc[mt][nt][half * 2 + 1]);
            }
        }
    }
}

// ---------------- flash attention with warp-MMA ----------------
// CTA: 128 Q rows x full Dh. 4 warps, warp owns 32 rows (2 mtiles).
// K/V tiles 64 keys. Qs[128][68], Ks[64][68], Vs[64][72], Ps[128][72].
#define QS_OFF 0
#define KS_OFF 8704
#define VS_OFF 13056
#define PS_OFF 17664

__global__ __launch_bounds__(128) void attn_mma() {
    extern __shared__ float sm[];
    float* Qs = sm + QS_OFF;
    float* Ks = sm + KS_OFF;
    float* Vs = sm + VS_OFF;
    float* Ps = sm + PS_OFF;

    const int tid = threadIdx.x;
    const int lane = tid & 31, wid = tid >> 5;
    const int qt = gridDim.x - 1 - blockIdx.x;   // heavy tiles first
    const int h = blockIdx.y, b = blockIdx.z;

    const float* Qg = g_Q + (((size_t)b * Hh + h) * Ss + (size_t)qt * 128) * DH;
    const float* Kg = g_K + (((size_t)b * Hh + h) * Ss) * DH;
    const float* Vg = g_V + (((size_t)b * Hh + h) * Ss) * DH;

    uint32_t sQ = smem_u32(Qs), sK = smem_u32(Ks), sV = smem_u32(Vs);

    // load Q tile (async)
    #pragma unroll
    for (int t = 0; t < 16; t++) {
        int idx = tid + t * 128;          // 0..2047
        int r = idx >> 4, c = (idx & 15) * 4;
        cp16(sQ + (r * 68 + c) * 4, Qg + r * DH + c);
    }
    cp_commit();

    float o[2][8][4];
    float mrow[2][2], lrow[2][2];
    #pragma unroll
    for (int mt = 0; mt < 2; mt++) {
        mrow[mt][0] = mrow[mt][1] = -1e30f;
        lrow[mt][0] = lrow[mt][1] = 0.f;
        #pragma unroll
        for (int nt = 0; nt < 8; nt++)
            #pragma unroll
            for (int q = 0; q < 4; q++) o[mt][nt][q] = 0.f;
    }

    const int cL = lane & 3, rL = lane >> 2;
    const int ktMax = 2 * qt + 1;

    for (int kt = 0; kt <= ktMax; kt++) {
        __syncthreads();   // K/V free (prev iter consumers done)
        const float* Kp = Kg + (size_t)kt * 64 * DH;
        const float* Vp = Vg + (size_t)kt * 64 * DH;
        #pragma unroll
        for (int t = 0; t < 8; t++) {
            int idx = tid + t * 128;      // 0..1023
            int r = idx >> 4, c = (idx & 15) * 4;
            cp16(sK + (r * 68 + c) * 4, Kp + r * DH + c);
            cp16(sV + (r * 72 + c) * 4, Vp + r * DH + c);
        }
        cp_commit();
        cp_wait0();
        __syncthreads();

        // S = Q K^T : warp rows wid*32..+31 (2 mtiles), cols 0..63 (8 ntiles)
        float s[2][8][4];
        #pragma unroll
        for (int mt = 0; mt < 2; mt++)
            #pragma unroll
            for (int nt = 0; nt < 8; nt++)
                #pragma unroll
                for (int q = 0; q < 4; q++) s[mt][nt][q] = 0.f;

        #pragma unroll
        for (int ks = 0; ks < 8; ks++) {
            const int kb = ks * 8 + cL;
            uint32_t bfr[8][2];
            #pragma unroll
            for (int nt = 0; nt < 8; nt++) {
                const float* kp = Ks + (nt * 8 + rL) * 68;
                bfr[nt][0] = f2u(kp[kb]);
                bfr[nt][1] = f2u(kp[kb + 4]);
            }
            #pragma unroll
            for (int mt = 0; mt < 2; mt++) {
                const float* qp = Qs + (wid * 32 + mt * 16 + rL) * 68;
                uint32_t a[4];
                a[0] = f2u(qp[kb]);
                a[1] = f2u(qp[8 * 68 + kb]);
                a[2] = f2u(qp[kb + 4]);
                a[3] = f2u(qp[8 * 68 + kb + 4]);
                #pragma unroll
                for (int nt = 0; nt < 8; nt++) mma8(s[mt][nt], a, bfr[nt]);
            }
        }

        // causal mask (only last two kt tiles can touch the diagonal)
        if (kt >= 2 * qt) {
            #pragma unroll
            for (int mt = 0; mt < 2; mt++) {
                int rg0 = qt * 128 + wid * 32 + mt * 16 + rL;
                #pragma unroll
                for (int nt = 0; nt < 8; nt++) {
                    int cg = kt * 64 + nt * 8 + 2 * cL;
                    if (cg     > rg0)     s[mt][nt][0] = -1e30f;
                    if (cg + 1 > rg0)     s[mt][nt][1] = -1e30f;
                    if (cg     > rg0 + 8) s[mt][nt][2] = -1e30f;
                    if (cg + 1 > rg0 + 8) s[mt][nt][3] = -1e30f;
                }
            }
        }

        // online softmax per mtile (rows r0, r0+8 per thread; quad = row group)
        #pragma unroll
        for (int mt = 0; mt < 2; mt++) {
            float v0 = -1e30f, v1 = -1e30f;
            #pragma unroll
            for (int nt = 0; nt < 8; nt++) {
                v0 = fmaxf(v0, fmaxf(s[mt][nt][0], s[mt][nt][1]));
                v1 = fmaxf(v1, fmaxf(s[mt][nt][2], s[mt][nt][3]));
            }
            v0 = fmaxf(v0, __shfl_xor_sync(0xffffffffu, v0, 1));
            v0 = fmaxf(v0, __shfl_xor_sync(0xffffffffu, v0, 2));
            v1 = fmaxf(v1, __shfl_xor_sync(0xffffffffu, v1, 1));
            v1 = fmaxf(v1, __shfl_xor_sync(0xffffffffu, v1, 2));

            float mn0 = fmaxf(mrow[mt][0], v0);
            float mn1 = fmaxf(mrow[mt][1], v1);
            float cr0 = __expf(mrow[mt][0] - mn0);
            float cr1 = __expf(mrow[mt][1] - mn1);
            mrow[mt][0] = mn0; mrow[mt][1] = mn1;

            float rs0 = 0.f, rs1 = 0.f;
            float* prow0 = Ps + (wid * 32 + mt * 16 + rL) * 72;
            float* prow1 = prow0 + 8 * 72;
            #pragma unroll
            for (int nt = 0; nt < 8; nt++) {
                float p0 = __expf(s[mt][nt][0] - mn0);
                float p1 = __expf(s[mt][nt][1] - mn0);
                float p2 = __expf(s[mt][nt][2] - mn1);
                float p3 = __expf(s[mt][nt][3] - mn1);
                rs0 += p0 + p1; rs1 += p2 + p3;
                int cc = nt * 8 + 2 * cL;
                *(float2*)(prow0 + cc) = make_float2(to_tf32(p0), to_tf32(p1));
                *(float2*)(prow1 + cc) = make_float2(to_tf32(p2), to_tf32(p3));
            }
            rs0 += __shfl_xor_sync(0xffffffffu, rs0, 1);
            rs0 += __shfl_xor_sync(0xffffffffu, rs0, 2);
            rs1 += __shfl_xor_sync(0xffffffffu, rs1, 1);
            rs1 += __shfl_xor_sync(0xffffffffu, rs1, 2);
            lrow[mt][0] = lrow[mt][0] * cr0 + rs0;
            lrow[mt][1] = lrow[mt][1] * cr1 + rs1;
            #pragma unroll
            for (int nt = 0; nt < 8; nt++) {
                o[mt][nt][0] *= cr0; o[mt][nt][1] *= cr0;
                o[mt][nt][2] *= cr1; o[mt][nt][3] *= cr1;
            }
        }
        __syncwarp();

        // O += P V  (A = Ps rows of this warp, B = Vs)
        #pragma unroll
        for (int ks = 0; ks < 8; ks++) {
            const int kb = ks * 8;
            uint32_t bfr[8][2];
            #pragma unroll
            for (int nt = 0; nt < 8; nt++) {
                bfr[nt][0] = f2u(Vs[(kb + cL) * 72 + nt * 8 + rL]);
                bfr[nt][1] = f2u(Vs[(kb + 4 + cL) * 72 + nt * 8 + rL]);
            }
            #pragma unroll
            for (int mt = 0; mt < 2; mt++) {
                const float* pp = Ps + (wid * 32 + mt * 16 + rL) * 72;
                uint32_t a[4];
                a[0] = f2u(pp[kb + cL]);
                a[1] = f2u(pp[8 * 72 + kb + cL]);
                a[2] = f2u(pp[kb + 4 + cL]);
                a[3] = f2u(pp[8 * 72 + kb + 4 + cL]);
                #pragma unroll
                for (int nt = 0; nt < 8; nt++) mma8(o[mt][nt], a, bfr[nt]);
            }
        }
    }

    // epilogue: normalize, round, store to g_O [B*S, 768]
    #pragma unroll
    for (int mt = 0; mt < 2; mt++) {
        float inv0 = 1.f / lrow[mt][0];
        float inv1 = 1.f / lrow[mt][1];
        int r0 = qt * 128 + wid * 32 + mt * 16 + rL;
        float* d0 = g_O + ((size_t)b * Ss + r0) * Dd + h * DH;
        float* d1 = d0 + 8 * Dd;
        #pragma unroll
        for (int nt = 0; nt < 8; nt++) {
            int cc = nt * 8 + 2 * cL;
            *(float2*)(d0 + cc) = make_float2(to_tf32(o[mt][nt][0] * inv0),
                                              to_tf32(o[mt][nt][1] * inv0));
            *(float2*)(d1 + cc) = make_float2(to_tf32(o[mt][nt][2] * inv1),
                                              to_tf32(o[mt][nt][3] * inv1));
        }
    }
}

// ---------------------------------------------------------------------------

extern "C" void kernel_launch(void* const* d_in, const int* in_sizes, int n_in,
                              void* d_out, int out_size)
{
    const float* x  = (const float*)d_in[0];
    const float* Wq = (const float*)d_in[1];
    const float* Wk = (const float*)d_in[2];
    const float* Wv = (const float*)d_in[3];
    const float* Wo = (const float*)d_in[4];
    float* out = (float*)d_out;

    const int GEMM_SMEM = 4 * GSTG * (int)sizeof(float);   // 81920
    const int ATTN_SMEM = (PS_OFF + 128 * 72) * (int)sizeof(float);  // 107520

    cudaFuncSetAttribute(gemm_qkv_tc, cudaFuncAttributeMaxDynamicSharedMemorySize, GEMM_SMEM);
    cudaFuncSetAttribute(gemm_out_tc, cudaFuncAttributeMaxDynamicSharedMemorySize, GEMM_SMEM);
    cudaFuncSetAttribute(attn_mma,    cudaFuncAttributeMaxDynamicSharedMemorySize, ATTN_SMEM);

    conv_all<<<512, 256>>>(x, Wq, Wk, Wv, Wo);
    gemm_qkv_tc<<<dim3(Mm / 128, Dd / 128, 3), 128, GEMM_SMEM>>>();
    attn_mma<<<dim3(Ss / 128, Hh, Bb), 128, ATTN_SMEM>>>();
    gemm_out_tc<<<dim3(Mm / 128, Dd / 128), 128, GEMM_SMEM>>>(out);
}